// round 15
// baseline (speedup 1.0000x reference)
#include <cuda_runtime.h>
#include <cuda_fp16.h>
#include <math.h>

#define NPTS 131072
#define NQ   1000
#define PPC  16
#define NTOT (NPTS + NQ + 2)
#define NTILES  8255             // ceil(132074/16)
#define NQTILES 63               // 63*16 = 1008 tail slots >= 1002
#define ROWP 528                 // bytes per A smem row (264 f16)
#define THREADS 256
#define GRID 296                 // 2 CTAs x 148 SMs, persistent

// smem map
#define SA    0                  // [48][264] f16 = 25344
#define SB2   25344              // b2 (1024)
#define SB3   26368              // b3 (1024)
#define SW4   27392              // W4 (1024)
#define SSV   28416              // 16 f32
#define SDRED 28480              // [3][16][8] f32 = 1536
#define SM_ALLOC 30080

__device__ float g_qw[NQ];
__device__ float g_duq[NQ];
__device__ float g_u0, g_uL;
// B fragments (fp16): [layer][wgn8][ks][j][lane] -> uint4
__device__ uint4 g_Bf[2][8][16][2][32];

// ---------------- PTX helpers (baseline, sm_80+) ----------------
__device__ __forceinline__ float tanhfast(float x) {
    float y;
    asm("tanh.approx.f32 %0, %1;" : "=f"(y) : "f"(x));
    return y;
}
__device__ __forceinline__ void ldsm4(unsigned& r0, unsigned& r1, unsigned& r2,
                                      unsigned& r3, unsigned addr) {
    asm volatile("ldmatrix.sync.aligned.m8n8.x4.shared.b16 {%0,%1,%2,%3}, [%4];"
                 : "=r"(r0), "=r"(r1), "=r"(r2), "=r"(r3) : "r"(addr));
}
__device__ __forceinline__ void mma16816(float* c, const unsigned* a,
                                         unsigned b0, unsigned b1) {
    asm volatile(
        "mma.sync.aligned.m16n8k16.row.col.f32.f16.f16.f32 "
        "{%0,%1,%2,%3}, {%4,%5,%6,%7}, {%8,%9}, {%0,%1,%2,%3};"
        : "+f"(c[0]), "+f"(c[1]), "+f"(c[2]), "+f"(c[3])
        : "r"(a[0]), "r"(a[1]), "r"(a[2]), "r"(a[3]), "r"(b0), "r"(b1));
}
__device__ __forceinline__ unsigned pack_h2(float a, float b) {
    __half2 t = __floats2half2_rn(a, b);
    return *(unsigned*)&t;
}
__device__ __forceinline__ void store_A(char* gb, int row, int k, float v0, float v1) {
    unsigned off = (unsigned)row * ROWP + (unsigned)k * 2;
    *(unsigned*)(gb + SA + off) = pack_h2(v0, v1);
}

// ---------------- prep: W2/W3 -> warp-unique fp16 fragments ----------------
__global__ void prep_kernel(const float* __restrict__ W2, const float* __restrict__ W3) {
    int idx = blockIdx.x * 256 + threadIdx.x;       // 16384 uint4
    int lane  = idx & 31;
    int j     = (idx >> 5)  & 1;
    int ks    = (idx >> 6)  & 15;
    int wgn   = (idx >> 10) & 7;
    int l     = (idx >> 13) & 1;
    const float* W = l ? W3 : W2;
    unsigned r[4];
    #pragma unroll
    for (int n8s = 0; n8s < 2; n8s++)
        #pragma unroll
        for (int kb = 0; kb < 2; kb++) {
            int n = wgn * 32 + (j * 2 + n8s) * 8 + (lane >> 2);
            int k = ks * 16 + kb * 8 + (lane & 3) * 2;
            r[n8s * 2 + kb] = pack_h2(W[k * 256 + n], W[(k + 1) * 256 + n]);
        }
    g_Bf[l][wgn][ks][j][lane] = make_uint4(r[0], r[1], r[2], r[3]);
}

// ---------------- fused MLP + 1st/2nd derivative (persistent) --------------
__global__ __launch_bounds__(THREADS, 2)
void mlp_kernel(const float* __restrict__ x,
                const float* __restrict__ W1, const float* __restrict__ b1,
                const float* __restrict__ b2, const float* __restrict__ b3,
                const float* __restrict__ W4, const float* __restrict__ b4,
                float* __restrict__ out)
{
    extern __shared__ unsigned char smraw[];
    char* gb = (char*)smraw;
    unsigned sb = (unsigned)__cvta_generic_to_shared(smraw);

    const int tid  = threadIdx.x;
    const int w    = tid >> 5;
    const int lane = tid & 31;
    const int wgn  = w;           // 0..7 : 32-col group
    const int bid  = blockIdx.x;

    // one-time table staging (persist across all tiles)
    ((float*)(gb + SW4))[tid] = W4[tid];
    ((float*)(gb + SB2))[tid] = b2[tid];
    ((float*)(gb + SB3))[tid] = b3[tid];
    const float b4v = b4[0];

    // ldmatrix lane base; per-use offset adds stream*16 rows
    const unsigned aA = sb + SA
        + (unsigned)(((lane >> 3) & 1) * 8 + (lane & 7)) * ROWP
        + (unsigned)((lane >> 4) << 4);

    #pragma unroll 1
    for (int tile_i = bid; tile_i < NTILES; tile_i += GRID) {
        const int tile  = (tile_i < NQTILES) ? (NTILES - NQTILES + tile_i)
                                             : (tile_i - NQTILES);
        const int gbase = tile * PPC;

        // ---- point inputs; quad tiles do Gauss-Legendre Newton in-CTA ----
        float sval = 0.0f;
        if (tid < PPC) {
            int gi = gbase + tid;
            if (gi < NPTS)                sval = x[gi];
            else if (gi == NPTS + NQ + 1) sval = 1.0f;      // u(L)
        }
        if (tile_i < NQTILES) {
            float* c1 = (float*)(gb + 0);      // scratch in A region (pre-seed)
            float* c2 = (float*)(gb + 12288);
            for (int j = tid + 1; j <= NQ; j += THREADS) {
                c1[j] = (2.0f * j - 1.0f) / (float)j;
                c2[j] = ((float)j - 1.0f) / (float)j;
            }
            __syncthreads();
            if (tid < PPC) {
                int qi = tile_i * PPC + tid;    // == (gbase + tid) - NPTS
                if (qi < NQ) {
                    float z = cospif((qi + 0.75f) / (NQ + 0.5f));
                    float p1 = 1.0f, p2 = 0.0f, pp = 1.0f;
                    #pragma unroll 1
                    for (int it = 0; it < 4; it++) {
                        p1 = 1.0f; p2 = 0.0f;
                        #pragma unroll 4
                        for (int j = 1; j <= NQ; j++) {
                            float p3 = p2; p2 = p1;
                            p1 = fmaf(c1[j] * z, p2, -(c2[j] * p3));
                        }
                        pp = (float)NQ * (z * p1 - p2) / (z * z - 1.0f);
                        z -= p1 / pp;
                    }
                    g_qw[qi] = 2.0f / ((1.0f - z * z) * pp * pp);
                    sval = 0.5f * z + 0.5f;
                }
            }
            __syncthreads();
        }
        if (tid < PPC) ((float*)(gb + SSV))[tid] = sval;
        __syncthreads();

        // ---- layer-1 seeds: rows p (h), 16+p (h'), 32+p (h'') ----
        {
            const float* sv = (const float*)(gb + SSV);
            for (int e = tid; e < PPC * 128; e += THREADS) {
                int p = e >> 7;
                int k = (e & 127) * 2;
                float s = sv[p];
                float2 wv = *(const float2*)&W1[k];
                float2 bv = *(const float2*)&b1[k];
                float h0 = tanhfast(fmaf(s, wv.x, bv.x));
                float h1 = tanhfast(fmaf(s, wv.y, bv.y));
                float g0 = 1.0f - h0 * h0, g1 = 1.0f - h1 * h1;
                float hp0 = g0 * wv.x, hp1 = g1 * wv.y;
                store_A(gb, p,      k, h0, h1);
                store_A(gb, 16 + p, k, hp0, hp1);
                store_A(gb, 32 + p, k, -2.0f * h0 * hp0 * wv.x, -2.0f * h1 * hp1 * wv.y);
            }
        }
        __syncthreads();

        #pragma unroll 1
        for (int l = 0; l < 2; l++) {
            float acc[3][4][4];     // [stream][n8][frag]
            #pragma unroll
            for (int s = 0; s < 3; s++)
                #pragma unroll
                for (int n8 = 0; n8 < 4; n8++)
                    #pragma unroll
                    for (int q = 0; q < 4; q++) acc[s][n8][q] = 0.0f;

            #pragma unroll 4
            for (int ks = 0; ks < 16; ks++) {
                uint4 bh0 = g_Bf[l][wgn][ks][0][lane];
                uint4 bh1 = g_Bf[l][wgn][ks][1][lane];
                unsigned ah[3][4];
                #pragma unroll
                for (int s = 0; s < 3; s++) {
                    unsigned ad = aA + (unsigned)(s * 16) * ROWP + (unsigned)ks * 32;
                    ldsm4(ah[s][0], ah[s][1], ah[s][2], ah[s][3], ad);
                }
                #pragma unroll
                for (int s = 0; s < 3; s++) {
                    mma16816(acc[s][0], ah[s], bh0.x, bh0.y);
                    mma16816(acc[s][1], ah[s], bh0.z, bh0.w);
                    mma16816(acc[s][2], ah[s], bh1.x, bh1.y);
                    mma16816(acc[s][3], ah[s], bh1.z, bh1.w);
                }
            }
            __syncthreads();   // all A reads done before epilogue overwrites A

            const float* bias = (const float*)(gb + (l ? SB3 : SB2));
            const float* w4s  = (const float*)(gb + SW4);

            if (l == 0) {
                // register-only tanh-chain coupling; write next-layer A
                #pragma unroll
                for (int n8 = 0; n8 < 4; n8++) {
                    int n0 = wgn * 32 + n8 * 8 + (lane & 3) * 2;
                    float bb0 = bias[n0], bb1 = bias[n0 + 1];
                    #pragma unroll
                    for (int rh = 0; rh < 2; rh++) {
                        int ci = rh * 2;
                        float z0  = acc[0][n8][ci] + bb0, z1  = acc[0][n8][ci + 1] + bb1;
                        float zp0 = acc[1][n8][ci],       zp1 = acc[1][n8][ci + 1];
                        float zq0 = acc[2][n8][ci],       zq1 = acc[2][n8][ci + 1];
                        float h0 = tanhfast(z0), h1 = tanhfast(z1);
                        float g0 = 1.0f - h0 * h0, g1 = 1.0f - h1 * h1;
                        float hp0 = g0 * zp0, hp1 = g1 * zp1;
                        float hq0 = fmaf(g0, zq0, -2.0f * h0 * hp0 * zp0);
                        float hq1 = fmaf(g1, zq1, -2.0f * h1 * hp1 * zp1);
                        int p = (lane >> 2) + rh * 8;
                        store_A(gb, p,      n0, h0, h1);
                        store_A(gb, 16 + p, n0, hp0, hp1);
                        store_A(gb, 32 + p, n0, hq0, hq1);
                    }
                }
                __syncthreads();
            } else {
                // final tanh + W4 dot over this warp's 32 cols, all 16 points
                float uu[2] = {0, 0}, du_[2] = {0, 0}, dd_[2] = {0, 0};
                #pragma unroll
                for (int n8 = 0; n8 < 4; n8++) {
                    int n0 = wgn * 32 + n8 * 8 + (lane & 3) * 2;
                    float bb0 = bias[n0], bb1 = bias[n0 + 1];
                    float w40 = w4s[n0], w41 = w4s[n0 + 1];
                    #pragma unroll
                    for (int rh = 0; rh < 2; rh++) {
                        int ci = rh * 2;
                        float z0  = acc[0][n8][ci] + bb0, z1  = acc[0][n8][ci + 1] + bb1;
                        float zp0 = acc[1][n8][ci],       zp1 = acc[1][n8][ci + 1];
                        float zq0 = acc[2][n8][ci],       zq1 = acc[2][n8][ci + 1];
                        float h0 = tanhfast(z0), h1 = tanhfast(z1);
                        float g0 = 1.0f - h0 * h0, g1 = 1.0f - h1 * h1;
                        float hp0 = g0 * zp0, hp1 = g1 * zp1;
                        float hq0 = fmaf(g0, zq0, -2.0f * h0 * hp0 * zp0);
                        float hq1 = fmaf(g1, zq1, -2.0f * h1 * hp1 * zp1);
                        uu[rh]  = fmaf(h0,  w40, fmaf(h1,  w41, uu[rh]));
                        du_[rh] = fmaf(hp0, w40, fmaf(hp1, w41, du_[rh]));
                        dd_[rh] = fmaf(hq0, w40, fmaf(hq1, w41, dd_[rh]));
                    }
                }
                float* dred = (float*)(gb + SDRED);
                #pragma unroll
                for (int rh = 0; rh < 2; rh++) {
                    float a = uu[rh], b = du_[rh], c = dd_[rh];
                    a += __shfl_xor_sync(0xffffffffu, a, 1);
                    a += __shfl_xor_sync(0xffffffffu, a, 2);
                    b += __shfl_xor_sync(0xffffffffu, b, 1);
                    b += __shfl_xor_sync(0xffffffffu, b, 2);
                    c += __shfl_xor_sync(0xffffffffu, c, 1);
                    c += __shfl_xor_sync(0xffffffffu, c, 2);
                    if ((lane & 3) == 0) {
                        int p = (lane >> 2) + rh * 8;
                        dred[(0 * 16 + p) * 8 + wgn] = a;
                        dred[(1 * 16 + p) * 8 + wgn] = b;
                        dred[(2 * 16 + p) * 8 + wgn] = c;
                    }
                }
                __syncthreads();
                if (w < 3 && lane < PPC) {
                    const float* dr = (const float*)(gb + SDRED) + (w * 16 + lane) * 8;
                    float v = ((dr[0] + dr[1]) + (dr[2] + dr[3]))
                            + ((dr[4] + dr[5]) + (dr[6] + dr[7]));
                    int gi = gbase + lane;
                    if (w == 0) {
                        v += b4v;
                        if (gi < NPTS) out[gi] = v;
                        else {
                            int qi = gi - NPTS;
                            if (qi == NQ)          g_u0 = v;
                            else if (qi == NQ + 1) g_uL = v;
                        }
                    } else if (w == 1) {
                        if (gi < NPTS) out[NPTS + gi] = v;
                        else { int qi = gi - NPTS; if (qi < NQ) g_duq[qi] = v; }
                    } else {
                        if (gi < NPTS) out[2 * NPTS + gi] = v;
                    }
                }
                __syncthreads();   // dred reads done before next tile reuses smem
            }
        }
    }
}

// ---------------- loss reduction ----------------
__global__ void loss_kernel(float* __restrict__ out) {
    __shared__ float red[256];
    float sacc = 0.0f;
    for (int i = threadIdx.x; i < NQ; i += 256) {
        const float d = g_duq[i];
        sacc = fmaf(g_qw[i] * d, d, sacc);
    }
    red[threadIdx.x] = sacc;
    __syncthreads();
    for (int o = 128; o; o >>= 1) {
        if (threadIdx.x < o) red[threadIdx.x] += red[threadIdx.x + o];
        __syncthreads();
    }
    if (threadIdx.x == 0)
        out[3 * NPTS] = (0.5f * red[0] - 5.0f * g_uL) + g_u0 * g_u0;
}

// ---------------- launch ----------------
extern "C" void kernel_launch(void* const* d_in, const int* in_sizes, int n_in,
                              void* d_out, int out_size)
{
    (void)in_sizes; (void)n_in; (void)out_size;
    const float* x  = (const float*)d_in[0];
    const float* W1 = (const float*)d_in[1];
    const float* b1 = (const float*)d_in[2];
    const float* W2 = (const float*)d_in[3];
    const float* b2 = (const float*)d_in[4];
    const float* W3 = (const float*)d_in[5];
    const float* b3 = (const float*)d_in[6];
    const float* W4 = (const float*)d_in[7];
    const float* b4 = (const float*)d_in[8];
    float* out = (float*)d_out;

    cudaFuncSetAttribute(mlp_kernel,
                         cudaFuncAttributeMaxDynamicSharedMemorySize, SM_ALLOC);

    prep_kernel<<<64, 256>>>(W2, W3);
    mlp_kernel<<<GRID, THREADS, SM_ALLOC>>>(x, W1, b1, b2, b3, W4, b4, out);
    loss_kernel<<<1, 256>>>(out);
}

// round 16
// speedup vs baseline: 1.0350x; 1.0350x over previous
#include <cuda_runtime.h>
#include <cuda_fp16.h>
#include <math.h>

#define NPTS 131072
#define NQ   1000
#define PPC  16
#define NTOT (NPTS + NQ + 2)
#define NTILES  8255             // ceil(132074/16); 16*8255 = 132080
#define NQTILES 63               // 63*16 = 1008 tail slots >= 1002
#define ROWP 528                 // bytes per A smem row (264 f16)
#define THREADS 256

// smem map (A fp16 + small tables)
#define SA    0                  // [48][264] f16 = 25344
#define SBIAS 25344
#define SW4   26368
#define SSV   27392
#define SDRED 27456              // [3][16][8] f32 = 1536
#define SM_ALLOC 29184

__device__ float g_qw[NQ];
__device__ float g_duq[NQ];
__device__ float g_u0, g_uL;
// B fragments (fp16): [layer][wgn8][ks][j][lane] -> uint4
__device__ uint4 g_Bf[2][8][16][2][32];

// ---------------- PTX helpers (baseline, sm_80+) ----------------
__device__ __forceinline__ float tanhfast(float x) {
    float y;
    asm("tanh.approx.f32 %0, %1;" : "=f"(y) : "f"(x));
    return y;
}
__device__ __forceinline__ void ldsm4(unsigned& r0, unsigned& r1, unsigned& r2,
                                      unsigned& r3, unsigned addr) {
    asm volatile("ldmatrix.sync.aligned.m8n8.x4.shared.b16 {%0,%1,%2,%3}, [%4];"
                 : "=r"(r0), "=r"(r1), "=r"(r2), "=r"(r3) : "r"(addr));
}
__device__ __forceinline__ void mma16816(float* c, const unsigned* a,
                                         unsigned b0, unsigned b1) {
    asm volatile(
        "mma.sync.aligned.m16n8k16.row.col.f32.f16.f16.f32 "
        "{%0,%1,%2,%3}, {%4,%5,%6,%7}, {%8,%9}, {%0,%1,%2,%3};"
        : "+f"(c[0]), "+f"(c[1]), "+f"(c[2]), "+f"(c[3])
        : "r"(a[0]), "r"(a[1]), "r"(a[2]), "r"(a[3]), "r"(b0), "r"(b1));
}
__device__ __forceinline__ unsigned pack_h2(float a, float b) {
    __half2 t = __floats2half2_rn(a, b);
    return *(unsigned*)&t;
}
__device__ __forceinline__ void store_A(char* gb, int row, int k, float v0, float v1) {
    unsigned off = (unsigned)row * ROWP + (unsigned)k * 2;
    *(unsigned*)(gb + SA + off) = pack_h2(v0, v1);
}

// ---------------- prep: W2/W3 -> warp-unique fp16 fragments ----------------
__global__ void prep_kernel(const float* __restrict__ W2, const float* __restrict__ W3) {
    int idx = blockIdx.x * 256 + threadIdx.x;       // 16384 uint4
    int lane  = idx & 31;
    int j     = (idx >> 5)  & 1;
    int ks    = (idx >> 6)  & 15;
    int wgn   = (idx >> 10) & 7;
    int l     = (idx >> 13) & 1;
    const float* W = l ? W3 : W2;
    unsigned r[4];
    #pragma unroll
    for (int n8s = 0; n8s < 2; n8s++)
        #pragma unroll
        for (int kb = 0; kb < 2; kb++) {
            int n = wgn * 32 + (j * 2 + n8s) * 8 + (lane >> 2);
            int k = ks * 16 + kb * 8 + (lane & 3) * 2;
            r[n8s * 2 + kb] = pack_h2(W[k * 256 + n], W[(k + 1) * 256 + n]);
        }
    g_Bf[l][wgn][ks][j][lane] = make_uint4(r[0], r[1], r[2], r[3]);
}

// ---------------- fused MLP + 1st/2nd derivative ----------------
__global__ __launch_bounds__(THREADS, 2)
void mlp_kernel(const float* __restrict__ x,
                const float* __restrict__ W1, const float* __restrict__ b1,
                const float* __restrict__ b2, const float* __restrict__ b3,
                const float* __restrict__ W4, const float* __restrict__ b4,
                float* __restrict__ out)
{
    extern __shared__ unsigned char smraw[];
    char* gb = (char*)smraw;
    unsigned sb = (unsigned)__cvta_generic_to_shared(smraw);

    const int tid  = threadIdx.x;
    const int w    = tid >> 5;
    const int lane = tid & 31;
    const int wgn  = w;           // 0..7 : 32-col group
    const int bid  = blockIdx.x;
    const int tile  = (bid < NQTILES) ? (NTILES - NQTILES + bid) : (bid - NQTILES);
    const int gbase = tile * PPC;

    ((float*)(gb + SW4))[tid] = W4[tid];
    const float b4v = b4[0];

    // ---- point inputs; quad tiles do Gauss-Legendre Newton in-CTA ----
    float sval = 0.0f;
    if (tid < PPC) {
        int gi = gbase + tid;
        if (gi < NPTS)                sval = x[gi];
        else if (gi == NPTS + NQ + 1) sval = 1.0f;      // u(L)
    }
    if (bid < NQTILES) {
        float* c1 = (float*)(gb + 0);      // scratch in A region (pre-seed)
        float* c2 = (float*)(gb + 12288);
        for (int j = tid + 1; j <= NQ; j += THREADS) {
            c1[j] = (2.0f * j - 1.0f) / (float)j;
            c2[j] = ((float)j - 1.0f) / (float)j;
        }
        __syncthreads();
        if (tid < PPC) {
            int qi = bid * PPC + tid;       // == (gbase + tid) - NPTS
            if (qi < NQ) {
                float z = cospif((qi + 0.75f) / (NQ + 0.5f));
                float p1 = 1.0f, p2 = 0.0f, pp = 1.0f;
                #pragma unroll 1
                for (int it = 0; it < 2; it++) {     // 2 Newton steps reach fp32 floor
                    p1 = 1.0f; p2 = 0.0f;
                    #pragma unroll 4
                    for (int j = 1; j <= NQ; j++) {
                        float p3 = p2; p2 = p1;
                        p1 = fmaf(c1[j] * z, p2, -(c2[j] * p3));
                    }
                    pp = (float)NQ * (z * p1 - p2) / (z * z - 1.0f);
                    z -= p1 / pp;
                }
                g_qw[qi] = 2.0f / ((1.0f - z * z) * pp * pp);
                sval = 0.5f * z + 0.5f;
            }
        }
        __syncthreads();
    }
    if (tid < PPC) ((float*)(gb + SSV))[tid] = sval;
    __syncthreads();

    // ---- layer-1 seeds: rows p (h), 16+p (h'), 32+p (h'') ----
    // vectorized: 4 k-pairs (8 cols) per iteration via float4 loads
    {
        const float* sv = (const float*)(gb + SSV);
        for (int e = tid; e < PPC * 32; e += THREADS) {
            int p  = e >> 5;
            int k0 = (e & 31) * 8;
            float s = sv[p];
            #pragma unroll
            for (int q = 0; q < 2; q++) {
                int k = k0 + q * 4;
                float4 wv = *(const float4*)&W1[k];
                float4 bv = *(const float4*)&b1[k];
                float h0 = tanhfast(fmaf(s, wv.x, bv.x));
                float h1 = tanhfast(fmaf(s, wv.y, bv.y));
                float h2 = tanhfast(fmaf(s, wv.z, bv.z));
                float h3 = tanhfast(fmaf(s, wv.w, bv.w));
                float g0 = 1.0f - h0 * h0, g1 = 1.0f - h1 * h1;
                float g2 = 1.0f - h2 * h2, g3 = 1.0f - h3 * h3;
                float hp0 = g0 * wv.x, hp1 = g1 * wv.y;
                float hp2 = g2 * wv.z, hp3 = g3 * wv.w;
                store_A(gb, p,      k,     h0, h1);
                store_A(gb, p,      k + 2, h2, h3);
                store_A(gb, 16 + p, k,     hp0, hp1);
                store_A(gb, 16 + p, k + 2, hp2, hp3);
                store_A(gb, 32 + p, k,     -2.0f * h0 * hp0 * wv.x, -2.0f * h1 * hp1 * wv.y);
                store_A(gb, 32 + p, k + 2, -2.0f * h2 * hp2 * wv.z, -2.0f * h3 * hp3 * wv.w);
            }
        }
    }
    __syncthreads();

    // ldmatrix lane base; per-use offset adds stream*16 rows
    const unsigned aA = sb + SA
        + (unsigned)(((lane >> 3) & 1) * 8 + (lane & 7)) * ROWP
        + (unsigned)((lane >> 4) << 4);

    #pragma unroll 1
    for (int l = 0; l < 2; l++) {
        ((float*)(gb + SBIAS))[tid] = (l ? b3 : b2)[tid];
        float acc[3][4][4];     // [stream][n8][frag]
        #pragma unroll
        for (int s = 0; s < 3; s++)
            #pragma unroll
            for (int n8 = 0; n8 < 4; n8++)
                #pragma unroll
                for (int q = 0; q < 4; q++) acc[s][n8][q] = 0.0f;

        #pragma unroll 4
        for (int ks = 0; ks < 16; ks++) {
            uint4 bh0 = g_Bf[l][wgn][ks][0][lane];
            uint4 bh1 = g_Bf[l][wgn][ks][1][lane];
            unsigned ah[3][4];
            #pragma unroll
            for (int s = 0; s < 3; s++) {
                unsigned ad = aA + (unsigned)(s * 16) * ROWP + (unsigned)ks * 32;
                ldsm4(ah[s][0], ah[s][1], ah[s][2], ah[s][3], ad);
            }
            #pragma unroll
            for (int s = 0; s < 3; s++) {
                mma16816(acc[s][0], ah[s], bh0.x, bh0.y);
                mma16816(acc[s][1], ah[s], bh0.z, bh0.w);
                mma16816(acc[s][2], ah[s], bh1.x, bh1.y);
                mma16816(acc[s][3], ah[s], bh1.z, bh1.w);
            }
        }
        __syncthreads();   // all A reads done before epilogue overwrites A

        const float* bias = (const float*)(gb + SBIAS);
        const float* w4s  = (const float*)(gb + SW4);

        if (l == 0) {
            // register-only tanh-chain coupling; write next-layer A
            #pragma unroll
            for (int n8 = 0; n8 < 4; n8++) {
                int n0 = wgn * 32 + n8 * 8 + (lane & 3) * 2;
                float bb0 = bias[n0], bb1 = bias[n0 + 1];
                #pragma unroll
                for (int rh = 0; rh < 2; rh++) {
                    int ci = rh * 2;
                    float z0  = acc[0][n8][ci] + bb0, z1  = acc[0][n8][ci + 1] + bb1;
                    float zp0 = acc[1][n8][ci],       zp1 = acc[1][n8][ci + 1];
                    float zq0 = acc[2][n8][ci],       zq1 = acc[2][n8][ci + 1];
                    float h0 = tanhfast(z0), h1 = tanhfast(z1);
                    float g0 = 1.0f - h0 * h0, g1 = 1.0f - h1 * h1;
                    float hp0 = g0 * zp0, hp1 = g1 * zp1;
                    float hq0 = fmaf(g0, zq0, -2.0f * h0 * hp0 * zp0);
                    float hq1 = fmaf(g1, zq1, -2.0f * h1 * hp1 * zp1);
                    int p = (lane >> 2) + rh * 8;
                    store_A(gb, p,      n0, h0, h1);
                    store_A(gb, 16 + p, n0, hp0, hp1);
                    store_A(gb, 32 + p, n0, hq0, hq1);
                }
            }
            __syncthreads();
        } else {
            // final tanh + W4 dot over this warp's 32 cols, all 16 points
            float uu[2] = {0, 0}, du_[2] = {0, 0}, dd_[2] = {0, 0};
            #pragma unroll
            for (int n8 = 0; n8 < 4; n8++) {
                int n0 = wgn * 32 + n8 * 8 + (lane & 3) * 2;
                float bb0 = bias[n0], bb1 = bias[n0 + 1];
                float w40 = w4s[n0], w41 = w4s[n0 + 1];
                #pragma unroll
                for (int rh = 0; rh < 2; rh++) {
                    int ci = rh * 2;
                    float z0  = acc[0][n8][ci] + bb0, z1  = acc[0][n8][ci + 1] + bb1;
                    float zp0 = acc[1][n8][ci],       zp1 = acc[1][n8][ci + 1];
                    float zq0 = acc[2][n8][ci],       zq1 = acc[2][n8][ci + 1];
                    float h0 = tanhfast(z0), h1 = tanhfast(z1);
                    float g0 = 1.0f - h0 * h0, g1 = 1.0f - h1 * h1;
                    float hp0 = g0 * zp0, hp1 = g1 * zp1;
                    float hq0 = fmaf(g0, zq0, -2.0f * h0 * hp0 * zp0);
                    float hq1 = fmaf(g1, zq1, -2.0f * h1 * hp1 * zp1);
                    uu[rh]  = fmaf(h0,  w40, fmaf(h1,  w41, uu[rh]));
                    du_[rh] = fmaf(hp0, w40, fmaf(hp1, w41, du_[rh]));
                    dd_[rh] = fmaf(hq0, w40, fmaf(hq1, w41, dd_[rh]));
                }
            }
            float* dred = (float*)(gb + SDRED);
            #pragma unroll
            for (int rh = 0; rh < 2; rh++) {
                float a = uu[rh], b = du_[rh], c = dd_[rh];
                a += __shfl_xor_sync(0xffffffffu, a, 1);
                a += __shfl_xor_sync(0xffffffffu, a, 2);
                b += __shfl_xor_sync(0xffffffffu, b, 1);
                b += __shfl_xor_sync(0xffffffffu, b, 2);
                c += __shfl_xor_sync(0xffffffffu, c, 1);
                c += __shfl_xor_sync(0xffffffffu, c, 2);
                if ((lane & 3) == 0) {
                    int p = (lane >> 2) + rh * 8;
                    dred[(0 * 16 + p) * 8 + wgn] = a;
                    dred[(1 * 16 + p) * 8 + wgn] = b;
                    dred[(2 * 16 + p) * 8 + wgn] = c;
                }
            }
            __syncthreads();
            if (w < 3 && lane < PPC) {
                const float* dr = (const float*)(gb + SDRED) + (w * 16 + lane) * 8;
                float v = ((dr[0] + dr[1]) + (dr[2] + dr[3]))
                        + ((dr[4] + dr[5]) + (dr[6] + dr[7]));
                int gi = gbase + lane;
                if (w == 0) {
                    v += b4v;
                    if (gi < NPTS) out[gi] = v;
                    else {
                        int qi = gi - NPTS;
                        if (qi == NQ)          g_u0 = v;
                        else if (qi == NQ + 1) g_uL = v;
                    }
                } else if (w == 1) {
                    if (gi < NPTS) out[NPTS + gi] = v;
                    else { int qi = gi - NPTS; if (qi < NQ) g_duq[qi] = v; }
                } else {
                    if (gi < NPTS) out[2 * NPTS + gi] = v;
                }
            }
        }
    }
}

// ---------------- loss reduction ----------------
__global__ void loss_kernel(float* __restrict__ out) {
    __shared__ float red[256];
    float sacc = 0.0f;
    for (int i = threadIdx.x; i < NQ; i += 256) {
        const float d = g_duq[i];
        sacc = fmaf(g_qw[i] * d, d, sacc);
    }
    red[threadIdx.x] = sacc;
    __syncthreads();
    for (int o = 128; o; o >>= 1) {
        if (threadIdx.x < o) red[threadIdx.x] += red[threadIdx.x + o];
        __syncthreads();
    }
    if (threadIdx.x == 0)
        out[3 * NPTS] = (0.5f * red[0] - 5.0f * g_uL) + g_u0 * g_u0;
}

// ---------------- launch ----------------
extern "C" void kernel_launch(void* const* d_in, const int* in_sizes, int n_in,
                              void* d_out, int out_size)
{
    (void)in_sizes; (void)n_in; (void)out_size;
    const float* x  = (const float*)d_in[0];
    const float* W1 = (const float*)d_in[1];
    const float* b1 = (const float*)d_in[2];
    const float* W2 = (const float*)d_in[3];
    const float* b2 = (const float*)d_in[4];
    const float* W3 = (const float*)d_in[5];
    const float* b3 = (const float*)d_in[6];
    const float* W4 = (const float*)d_in[7];
    const float* b4 = (const float*)d_in[8];
    float* out = (float*)d_out;

    cudaFuncSetAttribute(mlp_kernel,
                         cudaFuncAttributeMaxDynamicSharedMemorySize, SM_ALLOC);

    prep_kernel<<<64, 256>>>(W2, W3);
    mlp_kernel<<<NTILES, THREADS, SM_ALLOC>>>(x, W1, b1, b2, b3, W4, b4, out);
    loss_kernel<<<1, 256>>>(out);
}